// round 11
// baseline (speedup 1.0000x reference)
#include <cuda_runtime.h>
#include <cuda_bf16.h>
#include <cfloat>

// RegionSelector: B=128, C=1, H=W=512, GRID=4 (128x128 cells), WIN=3 -> 2x2
// windows, TOPK=1. Output dtype is float32 (checker convention, proven R8).
//
// Pass 1: 1024 blocks x 256 threads. Block = (batch, 64-row slab). Each slab
// lies entirely inside one 128-row grid band. Warp w (of 8) owns rows
// [slab*64 + w*8, +8); lane l reads float4s l, l+32, l+64, l+96 of each row
// -> each float4 entirely inside grid col 0..3 -> 4 register accumulators.
// Partials to __device__ scratch (no atomics; deterministic).
__device__ float g_partial[128 * 8 * 4];

__global__ __launch_bounds__(256) void rs_reduce(const float* __restrict__ in) {
    const int blk   = blockIdx.x;        // 0..1023
    const int b     = blk >> 3;          // batch
    const int chunk = blk & 7;           // 64-row slab

    const int tid  = threadIdx.x;
    const int w    = tid >> 5;           // warp 0..7
    const int lane = tid & 31;

    const float* base = in + (size_t)b * 512 * 512 + (size_t)chunk * 64 * 512;
    const int row0 = w * 8;

    float a0 = 0.f, a1 = 0.f, a2 = 0.f, a3 = 0.f;
    #pragma unroll
    for (int r = 0; r < 8; r += 2) {
        const float4* rp0 = (const float4*)(base + (size_t)(row0 + r) * 512);
        const float4* rp1 = (const float4*)(base + (size_t)(row0 + r + 1) * 512);
        float4 u0 = rp0[lane];      float4 u1 = rp0[lane + 32];
        float4 u2 = rp0[lane + 64]; float4 u3 = rp0[lane + 96];
        float4 v0 = rp1[lane];      float4 v1 = rp1[lane + 32];
        float4 v2 = rp1[lane + 64]; float4 v3 = rp1[lane + 96];
        a0 += ((u0.x + u0.y) + (u0.z + u0.w)) + ((v0.x + v0.y) + (v0.z + v0.w));
        a1 += ((u1.x + u1.y) + (u1.z + u1.w)) + ((v1.x + v1.y) + (v1.z + v1.w));
        a2 += ((u2.x + u2.y) + (u2.z + u2.w)) + ((v2.x + v2.y) + (v2.z + v2.w));
        a3 += ((u3.x + u3.y) + (u3.z + u3.w)) + ((v3.x + v3.y) + (v3.z + v3.w));
    }

    #pragma unroll
    for (int o = 16; o; o >>= 1) {
        a0 += __shfl_xor_sync(0xffffffffu, a0, o);
        a1 += __shfl_xor_sync(0xffffffffu, a1, o);
        a2 += __shfl_xor_sync(0xffffffffu, a2, o);
        a3 += __shfl_xor_sync(0xffffffffu, a3, o);
    }

    __shared__ float sm[8][4];
    if (lane == 0) { sm[w][0] = a0; sm[w][1] = a1; sm[w][2] = a2; sm[w][3] = a3; }
    __syncthreads();

    if (tid < 4) {
        float t = 0.f;
        #pragma unroll
        for (int ww = 0; ww < 8; ++ww) t += sm[ww][tid];
        g_partial[(b * 8 + chunk) * 4 + tid] = t;
    }
}

// Pass 2: one thread per batch. Combine 8x4 partials -> 4x4 cell means,
// 3x3 window sums, strict-> argmax (first-max tie-break == top_k), write
// (row, col) as float32.
__global__ __launch_bounds__(128) void rs_final(float* __restrict__ out) {
    const int b = threadIdx.x;

    float cell[4][4];
    #pragma unroll
    for (int gr = 0; gr < 4; ++gr)
        #pragma unroll
        for (int gc = 0; gc < 4; ++gc)
            cell[gr][gc] = (g_partial[(b * 8 + gr * 2 + 0) * 4 + gc] +
                            g_partial[(b * 8 + gr * 2 + 1) * 4 + gc]) *
                           (1.0f / 16384.0f);   // mean, as in reference

    float best = -FLT_MAX;
    int best_idx = 0;
    #pragma unroll
    for (int wr = 0; wr < 2; ++wr)
        #pragma unroll
        for (int wc = 0; wc < 2; ++wc) {
            float s = 0.f;
            #pragma unroll
            for (int r = 0; r < 3; ++r)
                #pragma unroll
                for (int c = 0; c < 3; ++c)
                    s += cell[wr + r][wc + c];
            const int idx = wr * 2 + wc;
            if (s > best) { best = s; best_idx = idx; }
        }

    out[b * 2 + 0] = (float)(best_idx >> 1);   // row = idx // 2
    out[b * 2 + 1] = (float)(best_idx & 1);    // col = idx %  2
}

extern "C" void kernel_launch(void* const* d_in, const int* in_sizes, int n_in,
                              void* d_out, int out_size) {
    const float* in = (const float*)d_in[0];
    float* out = (float*)d_out;
    rs_reduce<<<1024, 256>>>(in);
    rs_final<<<1, 128>>>(out);
}

// round 13
// speedup vs baseline: 1.0837x; 1.0837x over previous
#include <cuda_runtime.h>
#include <cuda_bf16.h>
#include <cfloat>

// RegionSelector: B=128, C=1, H=W=512, GRID=4 (128x128 cells), WIN=3 -> 2x2
// windows, TOPK=1. Output dtype float32 (checker convention, proven R8).
//
// Fused single kernel: 1024 blocks x 256 threads; block = (batch, 64-row
// slab). Each block reduces its slab to 4 column-cell partials in __device__
// scratch. The LAST block of each batch (atomic counter) performs the
// finalize inline: combine 8x4 partials -> 4x4 cell means -> 3x3 window sums
// -> strict-> argmax -> float (row, col). Deterministic: partials are a fixed
// function of the input; the finalizer reads them in fixed order.
__device__ float g_partial[128 * 8 * 4];
__device__ unsigned int g_count[128];   // zero-initialized; reset to 0 by finalizer

__global__ __launch_bounds__(256) void rs_fused(const float* __restrict__ in,
                                                float* __restrict__ out) {
    const int blk   = blockIdx.x;        // 0..1023
    const int b     = blk >> 3;          // batch
    const int chunk = blk & 7;           // 64-row slab

    const int tid  = threadIdx.x;
    const int w    = tid >> 5;           // warp 0..7
    const int lane = tid & 31;

    const float* base = in + (size_t)b * 512 * 512 + (size_t)chunk * 64 * 512;
    const int row0 = w * 8;

    float a0 = 0.f, a1 = 0.f, a2 = 0.f, a3 = 0.f;
    #pragma unroll
    for (int r = 0; r < 8; r += 2) {
        const float4* rp0 = (const float4*)(base + (size_t)(row0 + r) * 512);
        const float4* rp1 = (const float4*)(base + (size_t)(row0 + r + 1) * 512);
        float4 u0 = rp0[lane];      float4 u1 = rp0[lane + 32];
        float4 u2 = rp0[lane + 64]; float4 u3 = rp0[lane + 96];
        float4 v0 = rp1[lane];      float4 v1 = rp1[lane + 32];
        float4 v2 = rp1[lane + 64]; float4 v3 = rp1[lane + 96];
        a0 += ((u0.x + u0.y) + (u0.z + u0.w)) + ((v0.x + v0.y) + (v0.z + v0.w));
        a1 += ((u1.x + u1.y) + (u1.z + u1.w)) + ((v1.x + v1.y) + (v1.z + v1.w));
        a2 += ((u2.x + u2.y) + (u2.z + u2.w)) + ((v2.x + v2.y) + (v2.z + v2.w));
        a3 += ((u3.x + u3.y) + (u3.z + u3.w)) + ((v3.x + v3.y) + (v3.z + v3.w));
    }

    #pragma unroll
    for (int o = 16; o; o >>= 1) {
        a0 += __shfl_xor_sync(0xffffffffu, a0, o);
        a1 += __shfl_xor_sync(0xffffffffu, a1, o);
        a2 += __shfl_xor_sync(0xffffffffu, a2, o);
        a3 += __shfl_xor_sync(0xffffffffu, a3, o);
    }

    __shared__ float sm[8][4];
    __shared__ unsigned int s_last;
    if (lane == 0) { sm[w][0] = a0; sm[w][1] = a1; sm[w][2] = a2; sm[w][3] = a3; }
    __syncthreads();

    if (tid < 4) {
        float t = 0.f;
        #pragma unroll
        for (int ww = 0; ww < 8; ++ww) t += sm[ww][tid];
        g_partial[(b * 8 + chunk) * 4 + tid] = t;
    }
    __syncthreads();

    if (tid == 0) {
        __threadfence();                               // publish partials
        s_last = atomicAdd(&g_count[b], 1u);           // 7 => we are last
    }
    __syncthreads();

    if (s_last == 7u && tid == 0) {
        g_count[b] = 0u;                               // reset for graph replay
        __threadfence();                               // see others' partials

        float cell[4][4];
        #pragma unroll
        for (int gr = 0; gr < 4; ++gr)
            #pragma unroll
            for (int gc = 0; gc < 4; ++gc)
                cell[gr][gc] = (g_partial[(b * 8 + gr * 2 + 0) * 4 + gc] +
                                g_partial[(b * 8 + gr * 2 + 1) * 4 + gc]) *
                               (1.0f / 16384.0f);      // mean, as in reference

        float best = -FLT_MAX;
        int best_idx = 0;
        #pragma unroll
        for (int wr = 0; wr < 2; ++wr)
            #pragma unroll
            for (int wc = 0; wc < 2; ++wc) {
                float s = 0.f;
                #pragma unroll
                for (int r = 0; r < 3; ++r)
                    #pragma unroll
                    for (int c = 0; c < 3; ++c)
                        s += cell[wr + r][wc + c];
                const int idx = wr * 2 + wc;
                if (s > best) { best = s; best_idx = idx; }  // first-max == top_k
            }

        out[b * 2 + 0] = (float)(best_idx >> 1);   // row = idx // 2
        out[b * 2 + 1] = (float)(best_idx & 1);    // col = idx %  2
    }
}

extern "C" void kernel_launch(void* const* d_in, const int* in_sizes, int n_in,
                              void* d_out, int out_size) {
    const float* in = (const float*)d_in[0];
    float* out = (float*)d_out;
    rs_fused<<<1024, 256>>>(in, out);
}